// round 1
// baseline (speedup 1.0000x reference)
#include <cuda_runtime.h>

#define N_NODES 100000
#define N_REL 3
#define E_REL 800000
#define E_DEC 500000
#define D 64

// ---- scratch (no allocs allowed: __device__ globals) ----
__device__ float g_ns[N_REL * N_NODES];
__device__ float g_nd[N_REL * N_NODES];
__device__ int   g_odeg[N_REL * N_NODES];
__device__ int   g_ideg[N_REL * N_NODES];
__device__ float g_agg[(size_t)N_REL * N_NODES * D];   // 76.8 MB
__device__ float g_h1[(size_t)N_NODES * D];            // 25.6 MB
__device__ float g_h2[(size_t)N_NODES * D];            // 25.6 MB

__global__ void k_zero_deg() {
    int i = blockIdx.x * blockDim.x + threadIdx.x;
    if (i < N_REL * N_NODES) { g_odeg[i] = 0; g_ideg[i] = 0; }
}

__global__ void k_degree(const int* __restrict__ edges) {
    int t = blockIdx.x * blockDim.x + threadIdx.x;
    if (t >= N_REL * E_REL) return;
    int r = t / E_REL;
    int e = t - r * E_REL;
    int s = edges[(r * 2 + 0) * E_REL + e];
    int d = edges[(r * 2 + 1) * E_REL + e];
    atomicAdd(&g_odeg[r * N_NODES + s], 1);
    atomicAdd(&g_ideg[r * N_NODES + d], 1);
}

__global__ void k_norm() {
    int i = blockIdx.x * blockDim.x + threadIdx.x;
    if (i < N_REL * N_NODES) {
        g_ns[i] = rsqrtf((float)max(g_odeg[i], 1));
        g_nd[i] = rsqrtf((float)max(g_ideg[i], 1));
    }
}

__global__ void k_zero_agg() {
    size_t i = (size_t)blockIdx.x * blockDim.x + threadIdx.x;
    if (i < (size_t)N_REL * N_NODES * D / 4)
        reinterpret_cast<float4*>(g_agg)[i] = make_float4(0.f, 0.f, 0.f, 0.f);
}

// One warp per edge. Gather 256B row from `feat` (L2-hot), scale by ns[s]*nd[d],
// vector-reduce-add 256B into per-relation accumulator.
__global__ void __launch_bounds__(256) k_scatter(const int* __restrict__ edges,
                                                 const float* __restrict__ feat) {
    int e = blockIdx.x * 8 + (threadIdx.x >> 5);
    if (e >= E_REL) return;
    int r = blockIdx.y;
    int lane = threadIdx.x & 31;
    int s = edges[(r * 2 + 0) * E_REL + e];
    int d = edges[(r * 2 + 1) * E_REL + e];
    float c = g_ns[r * N_NODES + s] * g_nd[r * N_NODES + d];
    float2 v = *reinterpret_cast<const float2*>(feat + (size_t)s * D + lane * 2);
    float* dst = g_agg + (size_t)r * N_NODES * D + (size_t)d * D + lane * 2;
    asm volatile("red.global.add.v2.f32 [%0], {%1, %2};"
                 :: "l"(dst), "f"(v.x * c), "f"(v.y * c) : "memory");
}

// out[n] = (relu?)( sum_r agg_r[n] @ W_r + sum_r b_r )
// Per-relation 16KB W tile in smem; thread-per-node, 64 fp32 accumulators.
__global__ void __launch_bounds__(128) k_gemm(const float* __restrict__ W,
                                              const float* __restrict__ b,
                                              float* __restrict__ out,
                                              int do_relu) {
    __shared__ float sW[D * D];  // 16 KB, per-relation
    int n = blockIdx.x * 128 + threadIdx.x;

    float acc[D];
#pragma unroll
    for (int o = 0; o < D; o++) acc[o] = 0.f;

    for (int r = 0; r < N_REL; r++) {
        __syncthreads();
        for (int i = threadIdx.x; i < D * D / 4; i += 128)
            reinterpret_cast<float4*>(sW)[i] =
                reinterpret_cast<const float4*>(W + r * D * D)[i];
        __syncthreads();

        if (n < N_NODES) {
            const float4* arow = reinterpret_cast<const float4*>(
                g_agg + (size_t)r * N_NODES * D + (size_t)n * D);
#pragma unroll 2
            for (int i4 = 0; i4 < D / 4; i4++) {
                float4 a = arow[i4];
#pragma unroll
                for (int k = 0; k < 4; k++) {
                    float av = (k == 0) ? a.x : (k == 1) ? a.y : (k == 2) ? a.z : a.w;
                    const float4* wrow =
                        reinterpret_cast<const float4*>(sW + (i4 * 4 + k) * D);
#pragma unroll
                    for (int j = 0; j < D / 4; j++) {
                        float4 wv = wrow[j];
                        acc[4 * j + 0] += av * wv.x;
                        acc[4 * j + 1] += av * wv.y;
                        acc[4 * j + 2] += av * wv.z;
                        acc[4 * j + 3] += av * wv.w;
                    }
                }
            }
        }
    }

    if (n < N_NODES) {
        float4* orow = reinterpret_cast<float4*>(out + (size_t)n * D);
#pragma unroll
        for (int j = 0; j < D / 4; j++) {
            float4 v;
            float bx, by, bz, bw;
            bx = b[0 * D + 4 * j + 0] + b[1 * D + 4 * j + 0] + b[2 * D + 4 * j + 0];
            by = b[0 * D + 4 * j + 1] + b[1 * D + 4 * j + 1] + b[2 * D + 4 * j + 1];
            bz = b[0 * D + 4 * j + 2] + b[1 * D + 4 * j + 2] + b[2 * D + 4 * j + 2];
            bw = b[0 * D + 4 * j + 3] + b[1 * D + 4 * j + 3] + b[2 * D + 4 * j + 3];
            v.x = acc[4 * j + 0] + bx;
            v.y = acc[4 * j + 1] + by;
            v.z = acc[4 * j + 2] + bz;
            v.w = acc[4 * j + 3] + bw;
            if (do_relu) {
                v.x = fmaxf(v.x, 0.f); v.y = fmaxf(v.y, 0.f);
                v.z = fmaxf(v.z, 0.f); v.w = fmaxf(v.w, 0.f);
            }
            orow[j] = v;
        }
    }
}

// Edge scorer: one warp per dec edge. concat(h2[s], h2[d]) @ Wp + bp.
__global__ void __launch_bounds__(256) k_decoder(const int* __restrict__ dec,
                                                 const float* __restrict__ Wp,
                                                 const float* __restrict__ bp,
                                                 float* __restrict__ out) {
    __shared__ float sW[2 * D * N_REL];  // 384 floats
    __shared__ float sb[N_REL];
    for (int i = threadIdx.x; i < 2 * D * N_REL; i += blockDim.x) sW[i] = Wp[i];
    if (threadIdx.x < N_REL) sb[threadIdx.x] = bp[threadIdx.x];
    __syncthreads();

    int e = blockIdx.x * 8 + (threadIdx.x >> 5);
    if (e >= E_DEC) return;
    int lane = threadIdx.x & 31;
    int s = dec[e];
    int d = dec[E_DEC + e];
    float2 a  = *reinterpret_cast<const float2*>(g_h2 + (size_t)s * D + lane * 2);
    float2 bb = *reinterpret_cast<const float2*>(g_h2 + (size_t)d * D + lane * 2);

    int j0 = lane * 2;
    float p0, p1, p2;
    p0 = a.x  * sW[(j0 + 0) * 3 + 0] + a.y  * sW[(j0 + 1) * 3 + 0]
       + bb.x * sW[(D + j0 + 0) * 3 + 0] + bb.y * sW[(D + j0 + 1) * 3 + 0];
    p1 = a.x  * sW[(j0 + 0) * 3 + 1] + a.y  * sW[(j0 + 1) * 3 + 1]
       + bb.x * sW[(D + j0 + 0) * 3 + 1] + bb.y * sW[(D + j0 + 1) * 3 + 1];
    p2 = a.x  * sW[(j0 + 0) * 3 + 2] + a.y  * sW[(j0 + 1) * 3 + 2]
       + bb.x * sW[(D + j0 + 0) * 3 + 2] + bb.y * sW[(D + j0 + 1) * 3 + 2];

#pragma unroll
    for (int off = 16; off; off >>= 1) {
        p0 += __shfl_xor_sync(0xffffffffu, p0, off);
        p1 += __shfl_xor_sync(0xffffffffu, p1, off);
        p2 += __shfl_xor_sync(0xffffffffu, p2, off);
    }
    if (lane == 0) {
        out[(size_t)e * 3 + 0] = p0 + sb[0];
        out[(size_t)e * 3 + 1] = p1 + sb[1];
        out[(size_t)e * 3 + 2] = p2 + sb[2];
    }
}

extern "C" void kernel_launch(void* const* d_in, const int* in_sizes, int n_in,
                              void* d_out, int out_size) {
    (void)in_sizes; (void)n_in; (void)out_size;
    const float* x    = (const float*)d_in[0];
    const int*   edges= (const int*)d_in[1];
    const int*   dec  = (const int*)d_in[2];
    const float* W1   = (const float*)d_in[3];
    const float* b1   = (const float*)d_in[4];
    const float* W2   = (const float*)d_in[5];
    const float* b2   = (const float*)d_in[6];
    const float* Wp   = (const float*)d_in[7];
    const float* bp   = (const float*)d_in[8];
    float* out = (float*)d_out;

    void *p_h1 = nullptr, *p_h2 = nullptr;
    cudaGetSymbolAddress(&p_h1, g_h1);
    cudaGetSymbolAddress(&p_h2, g_h2);
    float* h1 = (float*)p_h1;
    float* h2 = (float*)p_h2;

    const int TB = 256;
    // degrees + norms (edges identical for both layers)
    k_zero_deg<<<(N_REL * N_NODES + TB - 1) / TB, TB>>>();
    k_degree<<<(N_REL * E_REL + TB - 1) / TB, TB>>>(edges);
    k_norm<<<(N_REL * N_NODES + TB - 1) / TB, TB>>>();

    dim3 sgrid((E_REL + 7) / 8, N_REL);
    int zgrid = (int)(((size_t)N_REL * N_NODES * D / 4 + TB - 1) / TB);
    int ggrid = (N_NODES + 127) / 128;

    // layer 1
    k_zero_agg<<<zgrid, TB>>>();
    k_scatter<<<sgrid, TB>>>(edges, x);
    k_gemm<<<ggrid, 128>>>(W1, b1, h1, 1);

    // layer 2
    k_zero_agg<<<zgrid, TB>>>();
    k_scatter<<<sgrid, TB>>>(edges, h1);
    k_gemm<<<ggrid, 128>>>(W2, b2, h2, 0);

    // decoder
    k_decoder<<<(E_DEC + 7) / 8, TB>>>(dec, Wp, bp, out);
}

// round 2
// speedup vs baseline: 1.4565x; 1.4565x over previous
#include <cuda_runtime.h>

#define N_NODES 100000
#define N_REL 3
#define E_REL 800000
#define E_DEC 500000
#define D 64

// ---- scratch (no allocs allowed: __device__ globals) ----
__device__ float g_ns[N_REL * N_NODES];
__device__ float g_nd[N_REL * N_NODES];
__device__ int   g_odeg[N_REL * N_NODES];
__device__ int   g_ideg[N_REL * N_NODES];
__device__ float g_agg[(size_t)N_REL * N_NODES * D];   // 76.8 MB
__device__ float g_h1[(size_t)N_NODES * D];            // 25.6 MB
__device__ float g_h2[(size_t)N_NODES * D];            // 25.6 MB

__global__ void k_zero_deg() {
    int i = blockIdx.x * blockDim.x + threadIdx.x;
    if (i < N_REL * N_NODES) { g_odeg[i] = 0; g_ideg[i] = 0; }
}

__global__ void k_degree(const int* __restrict__ edges) {
    int t = blockIdx.x * blockDim.x + threadIdx.x;
    if (t >= N_REL * E_REL) return;
    int r = t / E_REL;
    int e = t - r * E_REL;
    int s = edges[(r * 2 + 0) * E_REL + e];
    int d = edges[(r * 2 + 1) * E_REL + e];
    atomicAdd(&g_odeg[r * N_NODES + s], 1);
    atomicAdd(&g_ideg[r * N_NODES + d], 1);
}

__global__ void k_norm() {
    int i = blockIdx.x * blockDim.x + threadIdx.x;
    if (i < N_REL * N_NODES) {
        g_ns[i] = rsqrtf((float)max(g_odeg[i], 1));
        g_nd[i] = rsqrtf((float)max(g_ideg[i], 1));
    }
}

__global__ void k_zero_agg() {
    size_t i = (size_t)blockIdx.x * blockDim.x + threadIdx.x;
    if (i < (size_t)N_REL * N_NODES * D / 4)
        reinterpret_cast<float4*>(g_agg)[i] = make_float4(0.f, 0.f, 0.f, 0.f);
}

// Staged scatter: each warp owns 32 edges.
// Phase 1: lane e loads (s,d) + norms for edge base+e  (4 LDGs per 32 edges/lane).
// Phase 2: 16 steps; per step the warp processes 2 edges (16 lanes x float4 each):
//          1 LDG.128 gather + 1 red.global.add.v4.f32, indices via shfl broadcast.
__global__ void __launch_bounds__(256) k_scatter(const int* __restrict__ edges,
                                                 const float* __restrict__ feat) {
    int r = blockIdx.y;
    int warp = blockIdx.x * 8 + (threadIdx.x >> 5);
    int lane = threadIdx.x & 31;
    int base = warp * 32;                 // E_REL % 32 == 0, grid exact
    int e = base + lane;
    int s = edges[(r * 2 + 0) * E_REL + e];
    int d = edges[(r * 2 + 1) * E_REL + e];
    float c = g_ns[r * N_NODES + s] * g_nd[r * N_NODES + d];

    float* abase = g_agg + (size_t)r * N_NODES * D;
    int j = (lane & 15) * 4;              // float4 column offset
    int half = lane >> 4;                 // which of the 2 edges this step

#pragma unroll
    for (int k = 0; k < 16; k++) {
        int srcl = 2 * k + half;
        int ss = __shfl_sync(0xffffffffu, s, srcl);
        int dd = __shfl_sync(0xffffffffu, d, srcl);
        float cc = __shfl_sync(0xffffffffu, c, srcl);
        float4 v = *reinterpret_cast<const float4*>(feat + (size_t)ss * D + j);
        float* dst = abase + (size_t)dd * D + j;
        asm volatile("red.global.add.v4.f32 [%0], {%1, %2, %3, %4};"
                     :: "l"(dst), "f"(v.x * cc), "f"(v.y * cc),
                        "f"(v.z * cc), "f"(v.w * cc) : "memory");
    }
}

// out[n] = (relu?)( sum_r agg_r[n] @ W_r + sum_r b_r )
// Packed fp32x2 FMA (SASS FFMA2): 2x fp32 FMA throughput.
__global__ void __launch_bounds__(128) k_gemm(const float* __restrict__ W,
                                              const float* __restrict__ b,
                                              float* __restrict__ out,
                                              int do_relu) {
    __shared__ float sW[D * D];  // 16 KB, per-relation
    int n = blockIdx.x * 128 + threadIdx.x;

    unsigned long long acc[D / 2];  // 32 packed f32x2 accumulators
#pragma unroll
    for (int i = 0; i < D / 2; i++) acc[i] = 0ull;

    for (int r = 0; r < N_REL; r++) {
        __syncthreads();
        for (int i = threadIdx.x; i < D * D / 4; i += 128)
            reinterpret_cast<float4*>(sW)[i] =
                reinterpret_cast<const float4*>(W + r * D * D)[i];
        __syncthreads();

        if (n < N_NODES) {
            const float4* arow = reinterpret_cast<const float4*>(
                g_agg + (size_t)r * N_NODES * D + (size_t)n * D);
#pragma unroll
            for (int i4 = 0; i4 < D / 4; i4++) {
                float4 a = arow[i4];
                float av[4] = {a.x, a.y, a.z, a.w};
#pragma unroll
                for (int k = 0; k < 4; k++) {
                    unsigned long long av2;
                    asm("mov.b64 %0, {%1, %1};" : "=l"(av2) : "f"(av[k]));
                    const unsigned long long* wrow =
                        reinterpret_cast<const unsigned long long*>(
                            sW + (i4 * 4 + k) * D);
#pragma unroll
                    for (int jp = 0; jp < D / 2; jp++) {
                        asm("fma.rn.f32x2 %0, %1, %2, %0;"
                            : "+l"(acc[jp]) : "l"(av2), "l"(wrow[jp]));
                    }
                }
            }
        }
    }

    if (n < N_NODES) {
        float4* orow = reinterpret_cast<float4*>(out + (size_t)n * D);
#pragma unroll
        for (int q = 0; q < D / 4; q++) {
            float v0, v1, v2, v3;
            asm("mov.b64 {%0, %1}, %2;" : "=f"(v0), "=f"(v1) : "l"(acc[2 * q]));
            asm("mov.b64 {%0, %1}, %2;" : "=f"(v2), "=f"(v3) : "l"(acc[2 * q + 1]));
            int j = 4 * q;
            v0 += b[0 * D + j + 0] + b[1 * D + j + 0] + b[2 * D + j + 0];
            v1 += b[0 * D + j + 1] + b[1 * D + j + 1] + b[2 * D + j + 1];
            v2 += b[0 * D + j + 2] + b[1 * D + j + 2] + b[2 * D + j + 2];
            v3 += b[0 * D + j + 3] + b[1 * D + j + 3] + b[2 * D + j + 3];
            if (do_relu) {
                v0 = fmaxf(v0, 0.f); v1 = fmaxf(v1, 0.f);
                v2 = fmaxf(v2, 0.f); v3 = fmaxf(v3, 0.f);
            }
            orow[q] = make_float4(v0, v1, v2, v3);
        }
    }
}

// Edge scorer: one warp per dec edge. concat(h2[s], h2[d]) @ Wp + bp.
__global__ void __launch_bounds__(256) k_decoder(const int* __restrict__ dec,
                                                 const float* __restrict__ Wp,
                                                 const float* __restrict__ bp,
                                                 float* __restrict__ out) {
    __shared__ float sW[2 * D * N_REL];  // 384 floats
    __shared__ float sb[N_REL];
    for (int i = threadIdx.x; i < 2 * D * N_REL; i += blockDim.x) sW[i] = Wp[i];
    if (threadIdx.x < N_REL) sb[threadIdx.x] = bp[threadIdx.x];
    __syncthreads();

    int e = blockIdx.x * 8 + (threadIdx.x >> 5);
    if (e >= E_DEC) return;
    int lane = threadIdx.x & 31;
    int s = dec[e];
    int d = dec[E_DEC + e];
    float2 a  = *reinterpret_cast<const float2*>(g_h2 + (size_t)s * D + lane * 2);
    float2 bb = *reinterpret_cast<const float2*>(g_h2 + (size_t)d * D + lane * 2);

    int j0 = lane * 2;
    float p0, p1, p2;
    p0 = a.x  * sW[(j0 + 0) * 3 + 0] + a.y  * sW[(j0 + 1) * 3 + 0]
       + bb.x * sW[(D + j0 + 0) * 3 + 0] + bb.y * sW[(D + j0 + 1) * 3 + 0];
    p1 = a.x  * sW[(j0 + 0) * 3 + 1] + a.y  * sW[(j0 + 1) * 3 + 1]
       + bb.x * sW[(D + j0 + 0) * 3 + 1] + bb.y * sW[(D + j0 + 1) * 3 + 1];
    p2 = a.x  * sW[(j0 + 0) * 3 + 2] + a.y  * sW[(j0 + 1) * 3 + 2]
       + bb.x * sW[(D + j0 + 0) * 3 + 2] + bb.y * sW[(D + j0 + 1) * 3 + 2];

#pragma unroll
    for (int off = 16; off; off >>= 1) {
        p0 += __shfl_xor_sync(0xffffffffu, p0, off);
        p1 += __shfl_xor_sync(0xffffffffu, p1, off);
        p2 += __shfl_xor_sync(0xffffffffu, p2, off);
    }
    if (lane == 0) {
        out[(size_t)e * 3 + 0] = p0 + sb[0];
        out[(size_t)e * 3 + 1] = p1 + sb[1];
        out[(size_t)e * 3 + 2] = p2 + sb[2];
    }
}

extern "C" void kernel_launch(void* const* d_in, const int* in_sizes, int n_in,
                              void* d_out, int out_size) {
    (void)in_sizes; (void)n_in; (void)out_size;
    const float* x    = (const float*)d_in[0];
    const int*   edges= (const int*)d_in[1];
    const int*   dec  = (const int*)d_in[2];
    const float* W1   = (const float*)d_in[3];
    const float* b1   = (const float*)d_in[4];
    const float* W2   = (const float*)d_in[5];
    const float* b2   = (const float*)d_in[6];
    const float* Wp   = (const float*)d_in[7];
    const float* bp   = (const float*)d_in[8];
    float* out = (float*)d_out;

    void *p_h1 = nullptr, *p_h2 = nullptr;
    cudaGetSymbolAddress(&p_h1, g_h1);
    cudaGetSymbolAddress(&p_h2, g_h2);
    float* h1 = (float*)p_h1;
    float* h2 = (float*)p_h2;

    const int TB = 256;
    // degrees + norms (edges identical for both layers)
    k_zero_deg<<<(N_REL * N_NODES + TB - 1) / TB, TB>>>();
    k_degree<<<(N_REL * E_REL + TB - 1) / TB, TB>>>(edges);
    k_norm<<<(N_REL * N_NODES + TB - 1) / TB, TB>>>();

    dim3 sgrid(E_REL / 32 / 8, N_REL);   // 3125 x 3, exact
    int zgrid = (int)(((size_t)N_REL * N_NODES * D / 4 + TB - 1) / TB);
    int ggrid = (N_NODES + 127) / 128;

    // layer 1
    k_zero_agg<<<zgrid, TB>>>();
    k_scatter<<<sgrid, TB>>>(edges, x);
    k_gemm<<<ggrid, 128>>>(W1, b1, h1, 1);

    // layer 2
    k_zero_agg<<<zgrid, TB>>>();
    k_scatter<<<sgrid, TB>>>(edges, h1);
    k_gemm<<<ggrid, 128>>>(W2, b2, h2, 0);

    // decoder
    k_decoder<<<(E_DEC + 7) / 8, TB>>>(dec, Wp, bp, out);
}

// round 4
// speedup vs baseline: 1.5445x; 1.0604x over previous
#include <cuda_runtime.h>

#define N_NODES 100000
#define N_REL 3
#define E_REL 800000
#define E_DEC 500000
#define D 64
#define M_BUCKETS (N_REL * N_NODES)          // 300000
#define E_TOT (N_REL * E_REL)                // 2400000
#define SCAN_BS 512
#define N_SCAN_BLK ((M_BUCKETS + SCAN_BS - 1) / SCAN_BS)  // 586

// ---- scratch (__device__ globals; no allocs allowed) ----
__device__ float g_ns[M_BUCKETS];
__device__ float g_nd[M_BUCKETS];
__device__ int   g_odeg[M_BUCKETS];
__device__ int   g_ideg[M_BUCKETS];
__device__ int   g_off[M_BUCKETS + 1];
__device__ int   g_cur[M_BUCKETS];
__device__ int   g_bsum[1024];
__device__ int   g_esrc[E_TOT];                       // 9.6 MB
__device__ float g_t[(size_t)N_REL * N_NODES * D];    // 76.8 MB
__device__ float g_h1[(size_t)N_NODES * D];           // 25.6 MB
__device__ float g_h2[(size_t)N_NODES * D];           // 25.6 MB

__global__ void k_zero_deg() {
    int i = blockIdx.x * blockDim.x + threadIdx.x;
    if (i < M_BUCKETS) { g_odeg[i] = 0; g_ideg[i] = 0; }
}

__global__ void k_degree(const int* __restrict__ edges) {
    int t = blockIdx.x * blockDim.x + threadIdx.x;
    if (t >= E_TOT) return;
    int r = t / E_REL;
    int e = t - r * E_REL;
    int s = edges[(r * 2 + 0) * E_REL + e];
    int d = edges[(r * 2 + 1) * E_REL + e];
    atomicAdd(&g_odeg[r * N_NODES + s], 1);
    atomicAdd(&g_ideg[r * N_NODES + d], 1);
}

__global__ void k_norm() {
    int i = blockIdx.x * blockDim.x + threadIdx.x;
    if (i < M_BUCKETS) {
        g_ns[i] = rsqrtf((float)max(g_odeg[i], 1));
        g_nd[i] = rsqrtf((float)max(g_ideg[i], 1));
    }
}

// ---- 3-pass exclusive prefix scan of g_ideg -> g_off ----
__global__ void k_scan_a() {
    int i = blockIdx.x * SCAN_BS + threadIdx.x;
    int v = (i < M_BUCKETS) ? g_ideg[i] : 0;
    int lane = threadIdx.x & 31, wid = threadIdx.x >> 5;
    int inc = v;
#pragma unroll
    for (int o = 1; o < 32; o <<= 1) {
        int t = __shfl_up_sync(0xffffffffu, inc, o);
        if (lane >= o) inc += t;
    }
    __shared__ int wsum[SCAN_BS / 32];
    if (lane == 31) wsum[wid] = inc;
    __syncthreads();
    if (wid == 0) {
        int s = (lane < SCAN_BS / 32) ? wsum[lane] : 0;
#pragma unroll
        for (int o = 1; o < SCAN_BS / 32; o <<= 1) {
            int t = __shfl_up_sync(0xffffffffu, s, o);
            if (lane >= o) s += t;
        }
        if (lane < SCAN_BS / 32) wsum[lane] = s;
    }
    __syncthreads();
    int excl = inc - v + (wid > 0 ? wsum[wid - 1] : 0);
    if (i < M_BUCKETS) g_off[i] = excl;
    if (threadIdx.x == SCAN_BS - 1) g_bsum[blockIdx.x] = excl + v;
}

__global__ void k_scan_b() {
    int tid = threadIdx.x;                  // 1024 threads
    int v = (tid < N_SCAN_BLK) ? g_bsum[tid] : 0;
    int lane = tid & 31, wid = tid >> 5;
    int inc = v;
#pragma unroll
    for (int o = 1; o < 32; o <<= 1) {
        int t = __shfl_up_sync(0xffffffffu, inc, o);
        if (lane >= o) inc += t;
    }
    __shared__ int wsum[32];
    if (lane == 31) wsum[wid] = inc;
    __syncthreads();
    if (wid == 0) {
        int s = (lane < 32) ? wsum[lane] : 0;
#pragma unroll
        for (int o = 1; o < 32; o <<= 1) {
            int t = __shfl_up_sync(0xffffffffu, s, o);
            if (lane >= o) s += t;
        }
        wsum[lane] = s;
    }
    __syncthreads();
    int excl = inc - v + (wid > 0 ? wsum[wid - 1] : 0);
    if (tid < N_SCAN_BLK) g_bsum[tid] = excl;
}

__global__ void k_scan_c() {
    int i = blockIdx.x * blockDim.x + threadIdx.x;
    if (i < M_BUCKETS) {
        int off = g_off[i] + g_bsum[i / SCAN_BS];
        g_off[i] = off;
        g_cur[i] = off;
    }
    if (i == 0) g_off[M_BUCKETS] = E_TOT;
}

__global__ void k_fill(const int* __restrict__ edges) {
    int t = blockIdx.x * blockDim.x + threadIdx.x;
    if (t >= E_TOT) return;
    int r = t / E_REL;
    int e = t - r * E_REL;
    int s = edges[(r * 2 + 0) * E_REL + e];
    int d = edges[(r * 2 + 1) * E_REL + e];
    int pos = atomicAdd(&g_cur[r * N_NODES + d], 1);
    g_esrc[pos] = s;
}

// ---- GEMM-first: t_r[n] = (in[n] * ns_r[n]) @ W_r, for r=0..2 ----
__global__ void __launch_bounds__(128) k_mlp(const float* __restrict__ in,
                                             const float* __restrict__ W) {
    __shared__ float sW[D * D];  // 16 KB per relation
    int n = blockIdx.x * 128 + threadIdx.x;

    float4 xrow[D / 4];
    if (n < N_NODES) {
        const float4* xr = reinterpret_cast<const float4*>(in + (size_t)n * D);
#pragma unroll
        for (int i = 0; i < D / 4; i++) xrow[i] = xr[i];
    }

    for (int r = 0; r < N_REL; r++) {
        __syncthreads();
        for (int i = threadIdx.x; i < D * D / 4; i += 128)
            reinterpret_cast<float4*>(sW)[i] =
                reinterpret_cast<const float4*>(W + r * D * D)[i];
        __syncthreads();

        if (n < N_NODES) {
            float scale = g_ns[r * N_NODES + n];
            unsigned long long acc[D / 2];
#pragma unroll
            for (int i = 0; i < D / 2; i++) acc[i] = 0ull;

#pragma unroll
            for (int i4 = 0; i4 < D / 4; i4++) {
                float4 a = xrow[i4];
                float av[4] = {a.x * scale, a.y * scale, a.z * scale, a.w * scale};
#pragma unroll
                for (int k = 0; k < 4; k++) {
                    unsigned long long av2;
                    asm("mov.b64 %0, {%1, %1};" : "=l"(av2) : "f"(av[k]));
                    const unsigned long long* wrow =
                        reinterpret_cast<const unsigned long long*>(
                            sW + (i4 * 4 + k) * D);
#pragma unroll
                    for (int jp = 0; jp < D / 2; jp++) {
                        asm("fma.rn.f32x2 %0, %1, %2, %0;"
                            : "+l"(acc[jp]) : "l"(av2), "l"(wrow[jp]));
                    }
                }
            }
            float4* trow = reinterpret_cast<float4*>(
                g_t + ((size_t)r * N_NODES + n) * D);
#pragma unroll
            for (int q = 0; q < D / 4; q++) {
                float v0, v1, v2, v3;
                asm("mov.b64 {%0, %1}, %2;" : "=f"(v0), "=f"(v1) : "l"(acc[2 * q]));
                asm("mov.b64 {%0, %1}, %2;" : "=f"(v2), "=f"(v3) : "l"(acc[2 * q + 1]));
                trow[q] = make_float4(v0, v1, v2, v3);
            }
        }
    }
}

// ---- CSR aggregation: warp per dst. No atomics. Fused bias (+relu). ----
__global__ void __launch_bounds__(256) k_agg(float* __restrict__ out,
                                             const float* __restrict__ b,
                                             int do_relu) {
    __shared__ float sb[D];
    if (threadIdx.x < D)
        sb[threadIdx.x] = b[threadIdx.x] + b[D + threadIdx.x] + b[2 * D + threadIdx.x];
    __syncthreads();

    int d = blockIdx.x * 8 + (threadIdx.x >> 5);
    if (d >= N_NODES) return;
    int lane = threadIdx.x & 31;
    int j = (lane & 15) * 4;
    int half = lane >> 4;

    float4 tot = make_float4(0.f, 0.f, 0.f, 0.f);
#pragma unroll
    for (int r = 0; r < N_REL; r++) {
        int m = r * N_NODES + d;
        int start = g_off[m], end = g_off[m + 1];
        float4 acc = make_float4(0.f, 0.f, 0.f, 0.f);
        const float* tbase = g_t + (size_t)r * N_NODES * D;
        for (int i = start + half; i < end; i += 2) {
            int s = g_esrc[i];
            float4 v = *reinterpret_cast<const float4*>(tbase + (size_t)s * D + j);
            acc.x += v.x; acc.y += v.y; acc.z += v.z; acc.w += v.w;
        }
        float ndv = g_nd[m];
        tot.x += acc.x * ndv; tot.y += acc.y * ndv;
        tot.z += acc.z * ndv; tot.w += acc.w * ndv;
    }
    // combine the two halves (lane L with lane L+16, same j)
    tot.x += __shfl_xor_sync(0xffffffffu, tot.x, 16);
    tot.y += __shfl_xor_sync(0xffffffffu, tot.y, 16);
    tot.z += __shfl_xor_sync(0xffffffffu, tot.z, 16);
    tot.w += __shfl_xor_sync(0xffffffffu, tot.w, 16);

    if (half == 0) {
        tot.x += sb[j + 0]; tot.y += sb[j + 1];
        tot.z += sb[j + 2]; tot.w += sb[j + 3];
        if (do_relu) {
            tot.x = fmaxf(tot.x, 0.f); tot.y = fmaxf(tot.y, 0.f);
            tot.z = fmaxf(tot.z, 0.f); tot.w = fmaxf(tot.w, 0.f);
        }
        *reinterpret_cast<float4*>(out + (size_t)d * D + j) = tot;
    }
}

// ---- Edge scorer: one warp per dec edge ----
__global__ void __launch_bounds__(256) k_decoder(const int* __restrict__ dec,
                                                 const float* __restrict__ Wp,
                                                 const float* __restrict__ bp,
                                                 float* __restrict__ out) {
    __shared__ float sW[2 * D * N_REL];
    __shared__ float sb[N_REL];
    for (int i = threadIdx.x; i < 2 * D * N_REL; i += blockDim.x) sW[i] = Wp[i];
    if (threadIdx.x < N_REL) sb[threadIdx.x] = bp[threadIdx.x];
    __syncthreads();

    int e = blockIdx.x * 8 + (threadIdx.x >> 5);
    if (e >= E_DEC) return;
    int lane = threadIdx.x & 31;
    int s = dec[e];
    int d = dec[E_DEC + e];
    float2 a  = *reinterpret_cast<const float2*>(g_h2 + (size_t)s * D + lane * 2);
    float2 bb = *reinterpret_cast<const float2*>(g_h2 + (size_t)d * D + lane * 2);

    int j0 = lane * 2;
    float p0, p1, p2;
    p0 = a.x  * sW[(j0 + 0) * 3 + 0] + a.y  * sW[(j0 + 1) * 3 + 0]
       + bb.x * sW[(D + j0 + 0) * 3 + 0] + bb.y * sW[(D + j0 + 1) * 3 + 0];
    p1 = a.x  * sW[(j0 + 0) * 3 + 1] + a.y  * sW[(j0 + 1) * 3 + 1]
       + bb.x * sW[(D + j0 + 0) * 3 + 1] + bb.y * sW[(D + j0 + 1) * 3 + 1];
    p2 = a.x  * sW[(j0 + 0) * 3 + 2] + a.y  * sW[(j0 + 1) * 3 + 2]
       + bb.x * sW[(D + j0 + 0) * 3 + 2] + bb.y * sW[(D + j0 + 1) * 3 + 2];

#pragma unroll
    for (int off = 16; off; off >>= 1) {
        p0 += __shfl_xor_sync(0xffffffffu, p0, off);
        p1 += __shfl_xor_sync(0xffffffffu, p1, off);
        p2 += __shfl_xor_sync(0xffffffffu, p2, off);
    }
    if (lane == 0) {
        out[(size_t)e * 3 + 0] = p0 + sb[0];
        out[(size_t)e * 3 + 1] = p1 + sb[1];
        out[(size_t)e * 3 + 2] = p2 + sb[2];
    }
}

extern "C" void kernel_launch(void* const* d_in, const int* in_sizes, int n_in,
                              void* d_out, int out_size) {
    (void)in_sizes; (void)n_in; (void)out_size;
    const float* x    = (const float*)d_in[0];
    const int*   edges= (const int*)d_in[1];
    const int*   dec  = (const int*)d_in[2];
    const float* W1   = (const float*)d_in[3];
    const float* b1   = (const float*)d_in[4];
    const float* W2   = (const float*)d_in[5];
    const float* b2   = (const float*)d_in[6];
    const float* Wp   = (const float*)d_in[7];
    const float* bp   = (const float*)d_in[8];
    float* out = (float*)d_out;

    void *p_h1 = nullptr, *p_h2 = nullptr;
    cudaGetSymbolAddress(&p_h1, g_h1);
    cudaGetSymbolAddress(&p_h2, g_h2);
    float* h1 = (float*)p_h1;
    float* h2 = (float*)p_h2;

    const int TB = 256;
    // degrees + norms (edges identical for both layers)
    k_zero_deg<<<(M_BUCKETS + TB - 1) / TB, TB>>>();
    k_degree<<<(E_TOT + TB - 1) / TB, TB>>>(edges);
    k_norm<<<(M_BUCKETS + TB - 1) / TB, TB>>>();

    // CSR build (reused by both layers)
    k_scan_a<<<N_SCAN_BLK, SCAN_BS>>>();
    k_scan_b<<<1, 1024>>>();
    k_scan_c<<<(M_BUCKETS + TB - 1) / TB, TB>>>();
    k_fill<<<(E_TOT + TB - 1) / TB, TB>>>(edges);

    int ggrid = (N_NODES + 127) / 128;
    int agrid = (N_NODES + 7) / 8;

    // layer 1: t_r = (x . ns_r) @ W1_r ; h1 = relu(sum_r nd_r*agg(t_r) + sum b1_r)
    k_mlp<<<ggrid, 128>>>(x, W1);
    k_agg<<<agrid, TB>>>(h1, b1, 1);

    // layer 2
    k_mlp<<<ggrid, 128>>>(h1, W2);
    k_agg<<<agrid, TB>>>(h2, b2, 0);

    // decoder
    k_decoder<<<(E_DEC + 7) / 8, TB>>>(dec, Wp, bp, out);
}